// round 4
// baseline (speedup 1.0000x reference)
#include <cuda_runtime.h>
#include <math.h>

#define BB 16
#define TT 512
#define BT (BB*TT)
#define LOG2E 1.4426950408889634f

// ---------------- scratch (device globals; no allocation) ----------------
__device__ __align__(16) float g_o [BT*64];          // block-attn out [token][n*4+h*2+d]
__device__ __align__(16) float g_ab[BT*64];          // all_blocks
__device__ __align__(16) float g_cq[BT*64];          // cross q/k/v, [token][h*8+d]
__device__ __align__(16) float g_ck[BT*64];
__device__ __align__(16) float g_cv[BT*64];
__device__ __align__(16) float g_co[BT*64];          // cross attn out
__device__ float g_m [BB*8*TT];                      // log2-domain softmax bound [b*8+h][t]
__device__ float g_l [BB*8*TT];                      // softmax denom (exp2 sums)
__device__ float g_entp[BT*4];                       // entropy partials per s-chunk

__device__ __forceinline__ float gelu_exact(float x){
    return 0.5f*x*(1.0f + erff(x*0.70710678118654752f));
}

// ---------------- K2: fused block QKV + block attention (d=2) ----------------
// One CTA per (b, n, h). QKV computed inline from M. Single-pass softmax using
// Cauchy-Schwarz bound m = |q|*max|k| (log2 domain) instead of an exact-max pass.
__global__ void k2_blk_attn(const float* __restrict__ M,
                            const float* __restrict__ w,    // [16,12,4]
                            const float* __restrict__ bq){  // [16,12]
    __shared__ __align__(16) float4 skv[TT];  // {k0,k1,v0,v1} per s
    __shared__ float red[8];
    int bid = blockIdx.x;                     // 512 = b*32 + n*2 + h
    int b = bid >> 5;
    int n = (bid >> 1) & 15;
    int h = bid & 1;
    int tid = threadIdx.x;
    int br = n >> 2, bc = n & 3;
    float wq[2][4], wk[2][4], wv[2][4], bqv[2], bkv[2], bvv[2];
    #pragma unroll
    for (int e = 0; e < 2; e++){
        int rq = h*2 + e, rk = 4 + h*2 + e, rv = 8 + h*2 + e;
        #pragma unroll
        for (int c = 0; c < 4; c++){
            wq[e][c] = w[n*48 + rq*4 + c];
            wk[e][c] = w[n*48 + rk*4 + c];
            wv[e][c] = w[n*48 + rv*4 + c];
        }
        bqv[e] = bq[n*12 + rq]; bkv[e] = bq[n*12 + rk]; bvv[e] = bq[n*12 + rv];
    }
    const float qscale = 0.70710678118654752f * LOG2E;   // (1/sqrt(2))*log2(e)
    float q[2][2];
    float knmax = 0.f;
    #pragma unroll
    for (int qi = 0; qi < 2; qi++){
        int t = tid + qi*256;
        const float* Mtok = M + ((size_t)(b*TT + t))*64;
        float x0 = Mtok[(2*br+0)*8 + 2*bc+0];
        float x1 = Mtok[(2*br+0)*8 + 2*bc+1];
        float x2 = Mtok[(2*br+1)*8 + 2*bc+0];
        float x3 = Mtok[(2*br+1)*8 + 2*bc+1];
        float4 kv;
        kv.x = bkv[0] + wk[0][0]*x0 + wk[0][1]*x1 + wk[0][2]*x2 + wk[0][3]*x3;
        kv.y = bkv[1] + wk[1][0]*x0 + wk[1][1]*x1 + wk[1][2]*x2 + wk[1][3]*x3;
        kv.z = bvv[0] + wv[0][0]*x0 + wv[0][1]*x1 + wv[0][2]*x2 + wv[0][3]*x3;
        kv.w = bvv[1] + wv[1][0]*x0 + wv[1][1]*x1 + wv[1][2]*x2 + wv[1][3]*x3;
        skv[t] = kv;
        knmax = fmaxf(knmax, kv.x*kv.x + kv.y*kv.y);
        q[qi][0] = (bqv[0] + wq[0][0]*x0 + wq[0][1]*x1 + wq[0][2]*x2 + wq[0][3]*x3)*qscale;
        q[qi][1] = (bqv[1] + wq[1][0]*x0 + wq[1][1]*x1 + wq[1][2]*x2 + wq[1][3]*x3)*qscale;
    }
    // CTA max of |k|^2
    #pragma unroll
    for (int o = 16; o > 0; o >>= 1)
        knmax = fmaxf(knmax, __shfl_xor_sync(0xffffffffu, knmax, o));
    if ((tid & 31) == 0) red[tid >> 5] = knmax;
    __syncthreads();
    float kn = red[0];
    #pragma unroll
    for (int i = 1; i < 8; i++) kn = fmaxf(kn, red[i]);
    float mk = sqrtf(kn);
    // bounds (log2 domain; q already carries scale*log2e)
    float m0 = sqrtf(q[0][0]*q[0][0] + q[0][1]*q[0][1]) * mk;
    float m1 = sqrtf(q[1][0]*q[1][0] + q[1][1]*q[1][1]) * mk;
    float l0 = 0.f, a00 = 0.f, a01 = 0.f;
    float l1 = 0.f, a10 = 0.f, a11 = 0.f;
    for (int s = 0; s < TT; s++){
        float4 kv = skv[s];
        float p0 = exp2f(fmaf(q[0][0], kv.x, fmaf(q[0][1], kv.y, -m0)));
        float p1 = exp2f(fmaf(q[1][0], kv.x, fmaf(q[1][1], kv.y, -m1)));
        l0 += p0; a00 += p0*kv.z; a01 += p0*kv.w;
        l1 += p1; a10 += p1*kv.z; a11 += p1*kv.w;
    }
    float inv0 = 1.f/l0, inv1 = 1.f/l1;
    int o0 = (b*TT + tid      )*64 + n*4 + h*2;
    int o1 = (b*TT + tid + 256)*64 + n*4 + h*2;
    g_o[o0] = a00*inv0; g_o[o0+1] = a01*inv0;
    g_o[o1] = a10*inv1; g_o[o1+1] = a11*inv1;
}

// ---------------- K3: block-out proj + cross QKV (4 tokens per CTA) ----------------
__global__ void k3_proj_cqkv(const float* __restrict__ wout, // [16,4,4]
                             const float* __restrict__ bout, // [16,4]
                             const float* __restrict__ cw,   // [192,64]
                             const float* __restrict__ cb){  // [192]
    __shared__ __align__(16) float so [4][64];
    __shared__ __align__(16) float sab[4][64];
    int tid = threadIdx.x;
    int g = tid >> 6, j = tid & 63;
    int token = blockIdx.x*4 + g;
    so[g][j] = g_o[token*64 + j];
    __syncthreads();
    int n = j >> 2, e = j & 3;
    const float* wr = &wout[n*16 + e*4];
    float acc = bout[j] + wr[0]*so[g][n*4] + wr[1]*so[g][n*4+1]
              + wr[2]*so[g][n*4+2] + wr[3]*so[g][n*4+3];
    sab[g][j] = acc;
    g_ab[token*64 + j] = acc;
    __syncthreads();
    const float4* x4 = (const float4*)sab[g];
    #pragma unroll
    for (int rr = 0; rr < 3; rr++){
        int r = rr*64 + j;
        const float4* w4 = (const float4*)&cw[r*64];
        float acc2 = cb[r];
        #pragma unroll
        for (int k = 0; k < 16; k++){
            float4 w = w4[k], x = x4[k];
            acc2 += w.x*x.x + w.y*x.y + w.z*x.z + w.w*x.w;
        }
        float* dst = (rr==0) ? g_cq : (rr==1) ? g_ck : g_cv;
        dst[token*64 + j] = acc2;
    }
}

// ---------------- K4: cross attention (d=8), one CTA per (b,h) ----------------
// Single pass with Cauchy-Schwarz bound; stores log2-domain bound m'' and l.
__global__ void k4_cross_attn(){
    __shared__ __align__(16) float sk[TT*8];
    __shared__ __align__(16) float sv[TT*8];
    __shared__ float red[8];
    int bid = blockIdx.x;                    // 128
    int b = bid >> 3, h = bid & 7;
    int tid = threadIdx.x;
    float knmax = 0.f;
    for (int i = tid; i < TT; i += 256){
        int src = (b*TT + i)*64 + h*8;
        float4 ka = *(const float4*)&g_ck[src];
        float4 kb = *(const float4*)&g_ck[src+4];
        ((float4*)sk)[i*2  ] = ka;
        ((float4*)sk)[i*2+1] = kb;
        knmax = fmaxf(knmax, ka.x*ka.x + ka.y*ka.y + ka.z*ka.z + ka.w*ka.w
                           + kb.x*kb.x + kb.y*kb.y + kb.z*kb.z + kb.w*kb.w);
        ((float4*)sv)[i*2  ] = *(const float4*)&g_cv[src];
        ((float4*)sv)[i*2+1] = *(const float4*)&g_cv[src+4];
    }
    #pragma unroll
    for (int o = 16; o > 0; o >>= 1)
        knmax = fmaxf(knmax, __shfl_xor_sync(0xffffffffu, knmax, o));
    if ((tid & 31) == 0) red[tid >> 5] = knmax;
    __syncthreads();
    float kn = red[0];
    #pragma unroll
    for (int i = 1; i < 8; i++) kn = fmaxf(kn, red[i]);
    float mk = sqrtf(kn);
    const float qscale = 0.35355339059327376f * LOG2E;   // (1/sqrt(8))*log2(e)
    float q[2][8];
    float m[2];
    #pragma unroll
    for (int qi = 0; qi < 2; qi++){
        int t = tid + qi*256;
        float4 qa = *(const float4*)&g_cq[(b*TT+t)*64 + h*8];
        float4 qb = *(const float4*)&g_cq[(b*TT+t)*64 + h*8 + 4];
        q[qi][0]=qa.x*qscale; q[qi][1]=qa.y*qscale; q[qi][2]=qa.z*qscale; q[qi][3]=qa.w*qscale;
        q[qi][4]=qb.x*qscale; q[qi][5]=qb.y*qscale; q[qi][6]=qb.z*qscale; q[qi][7]=qb.w*qscale;
        float qn = 0.f;
        #pragma unroll
        for (int d = 0; d < 8; d++) qn += q[qi][d]*q[qi][d];
        m[qi] = sqrtf(qn) * mk;
    }
    float l0 = 0.f, l1 = 0.f;
    float a0[8], a1[8];
    #pragma unroll
    for (int d = 0; d < 8; d++){ a0[d] = 0.f; a1[d] = 0.f; }
    for (int s = 0; s < TT; s++){
        const float4* kr = (const float4*)&sk[s*8];
        float4 k0 = kr[0], k1 = kr[1];
        float x0 = -m[0], x1 = -m[1];
        x0 = fmaf(q[0][0],k0.x, fmaf(q[0][1],k0.y, fmaf(q[0][2],k0.z, fmaf(q[0][3],k0.w,
             fmaf(q[0][4],k1.x, fmaf(q[0][5],k1.y, fmaf(q[0][6],k1.z, fmaf(q[0][7],k1.w, x0))))))));
        x1 = fmaf(q[1][0],k0.x, fmaf(q[1][1],k0.y, fmaf(q[1][2],k0.z, fmaf(q[1][3],k0.w,
             fmaf(q[1][4],k1.x, fmaf(q[1][5],k1.y, fmaf(q[1][6],k1.z, fmaf(q[1][7],k1.w, x1))))))));
        float p0 = exp2f(x0);
        float p1 = exp2f(x1);
        const float4* vr = (const float4*)&sv[s*8];
        float4 v0 = vr[0], v1 = vr[1];
        l0 += p0; l1 += p1;
        a0[0]+=p0*v0.x; a0[1]+=p0*v0.y; a0[2]+=p0*v0.z; a0[3]+=p0*v0.w;
        a0[4]+=p0*v1.x; a0[5]+=p0*v1.y; a0[6]+=p0*v1.z; a0[7]+=p0*v1.w;
        a1[0]+=p1*v0.x; a1[1]+=p1*v0.y; a1[2]+=p1*v0.z; a1[3]+=p1*v0.w;
        a1[4]+=p1*v1.x; a1[5]+=p1*v1.y; a1[6]+=p1*v1.z; a1[7]+=p1*v1.w;
    }
    float inv0 = 1.f/l0, inv1 = 1.f/l1;
    int t0 = tid, t1 = tid + 256;
    int ob0 = (b*TT+t0)*64 + h*8, ob1 = (b*TT+t1)*64 + h*8;
    #pragma unroll
    for (int d = 0; d < 8; d++){ g_co[ob0+d] = a0[d]*inv0; g_co[ob1+d] = a1[d]*inv1; }
    g_m[(b*8+h)*TT + t0] = m[0]; g_l[(b*8+h)*TT + t0] = l0;
    g_m[(b*8+h)*TT + t1] = m[1]; g_l[(b*8+h)*TT + t1] = l1;
}

// ---------------- K5: entropy of head-averaged attention (score recompute) ----------------
// grid (16, 4 s-chunks, 4 q-chunks), 128 threads; K chunk in smem, q in regs.
// p_h-contribution folded entirely into the exp2 argument: p += exp2(dot'' - c_h),
// c_h = m''_h + 3 + log2(l_h).
__global__ void k5_entropy(){
    __shared__ __align__(16) float sks[128*64];
    int b  = blockIdx.x;
    int s0 = blockIdx.y * 128;
    int q0 = blockIdx.z * 128;
    int tid = threadIdx.x;                   // 128
    for (int i = tid; i < 128*16; i += 128){ // float4s
        int row = i >> 4, part = i & 15;
        ((float4*)sks)[i] = *(const float4*)&g_ck[(b*TT + s0 + row)*64 + part*4];
    }
    __syncthreads();
    int t = q0 + tid;
    const float qscale = 0.35355339059327376f * LOG2E;
    float4 qv[16];
    const float4* qg = (const float4*)&g_cq[(b*TT+t)*64];
    #pragma unroll
    for (int i = 0; i < 16; i++){
        float4 q = qg[i];
        q.x *= qscale; q.y *= qscale; q.z *= qscale; q.w *= qscale;
        qv[i] = q;
    }
    float ch[8];
    #pragma unroll
    for (int h = 0; h < 8; h++){
        ch[h] = g_m[(b*8+h)*TT + t] + 3.0f + __log2f(g_l[(b*8+h)*TT + t]);
    }
    float ent = 0.f;
    for (int s = 0; s < 128; s++){
        const float4* kr = (const float4*)&sks[s*64];
        float p = 0.f;
        #pragma unroll
        for (int h = 0; h < 8; h++){
            float4 k0 = kr[2*h], k1 = kr[2*h+1];
            float4 a0 = qv[2*h], a1 = qv[2*h+1];
            float d = -ch[h];
            d = fmaf(a0.x,k0.x, fmaf(a0.y,k0.y, fmaf(a0.z,k0.z, fmaf(a0.w,k0.w,
                fmaf(a1.x,k1.x, fmaf(a1.y,k1.y, fmaf(a1.z,k1.z, fmaf(a1.w,k1.w, d))))))));
            p += exp2f(d);
        }
        ent += p * __logf(p + 1e-9f);
    }
    g_entp[(b*TT+t)*4 + blockIdx.y] = -ent;
}

// ---------------- K6: cross-out proj + LN1 + FFN + LN2 + sens MLP + gate ----------------
__global__ void k6_final(const float* __restrict__ M, const int* __restrict__ tok_ids,
                         const float* __restrict__ cwout, const float* __restrict__ cbout,
                         const float* __restrict__ ln1g, const float* __restrict__ ln1b,
                         const float* __restrict__ fw1,  const float* __restrict__ fb1,
                         const float* __restrict__ fw2,  const float* __restrict__ fb2,
                         const float* __restrict__ ln2g, const float* __restrict__ ln2b,
                         const float* __restrict__ sbase,const float* __restrict__ taff,
                         const float* __restrict__ sw1,  const float* __restrict__ sb1,
                         const float* __restrict__ sw2,  const float* __restrict__ sb2,
                         float* __restrict__ out){
    __shared__ __align__(16) float sx [4][64];
    __shared__ __align__(16) float sy [4][64];
    __shared__ __align__(16) float sh1[4][256];
    __shared__ float sfeat[4][17];
    __shared__ float shh[4][32];
    __shared__ float ssen[4][16];
    int tid = threadIdx.x;
    int g = tid >> 6, j = tid & 63;
    int token = blockIdx.x*4 + g;
    sx[g][j] = g_co[token*64 + j];
    __syncthreads();
    float acc = cbout[j];
    {
        const float4* w4 = (const float4*)&cwout[j*64];
        const float4* x4 = (const float4*)sx[g];
        #pragma unroll
        for (int k = 0; k < 16; k++){
            float4 w = w4[k], x = x4[k];
            acc += w.x*x.x + w.y*x.y + w.z*x.z + w.w*x.w;
        }
    }
    float xj = g_ab[token*64 + j] + acc;
    __syncthreads();
    sx[g][j] = xj;
    __syncthreads();
    float sum = 0.f, ss = 0.f;
    #pragma unroll
    for (int k = 0; k < 64; k++){ float v = sx[g][k]; sum += v; ss += v*v; }
    float mu  = sum*(1.f/64.f);
    float var = ss*(1.f/64.f) - mu*mu;
    float rs  = rsqrtf(var + 1e-5f);
    float y = (xj - mu)*rs*ln1g[j] + ln1b[j];
    sy[g][j] = y;
    __syncthreads();
    #pragma unroll
    for (int rr = 0; rr < 4; rr++){
        int r = rr*64 + j;
        float a = fb1[r];
        const float4* w4 = (const float4*)&fw1[r*64];
        const float4* x4 = (const float4*)sy[g];
        #pragma unroll
        for (int k = 0; k < 16; k++){ float4 w=w4[k], x=x4[k]; a += w.x*x.x + w.y*x.y + w.z*x.z + w.w*x.w; }
        sh1[g][r] = gelu_exact(a);
    }
    __syncthreads();
    float a2 = fb2[j];
    {
        const float4* w4 = (const float4*)&fw2[j*256];
        const float4* x4 = (const float4*)sh1[g];
        #pragma unroll
        for (int k = 0; k < 64; k++){ float4 w=w4[k], x=x4[k]; a2 += w.x*x.x + w.y*x.y + w.z*x.z + w.w*x.w; }
    }
    float x2 = y + a2;
    __syncthreads();
    sx[g][j] = x2;
    __syncthreads();
    sum = 0.f; ss = 0.f;
    #pragma unroll
    for (int k = 0; k < 64; k++){ float v = sx[g][k]; sum += v; ss += v*v; }
    mu  = sum*(1.f/64.f);
    var = ss*(1.f/64.f) - mu*mu;
    rs  = rsqrtf(var + 1e-5f);
    float z = (x2 - mu)*rs*ln2g[j] + ln2b[j];
    if (j < 16) sfeat[g][j] = taff[(long long)tok_ids[token]*16 + j];
    if (j == 16){
        sfeat[g][16] = g_entp[token*4] + g_entp[token*4+1]
                     + g_entp[token*4+2] + g_entp[token*4+3];
    }
    __syncthreads();
    if (j < 32){
        float a = sb1[j];
        #pragma unroll
        for (int k = 0; k < 17; k++) a += sw1[j*17+k]*sfeat[g][k];
        shh[g][j] = gelu_exact(a);
    }
    __syncthreads();
    if (j < 16){
        float a = sb2[j];
        #pragma unroll
        for (int k = 0; k < 32; k++) a += sw2[j*32+k]*shh[g][k];
        ssen[g][j] = sbase[j] / (1.f + __expf(-a));
    }
    __syncthreads();
    float Mf = M[token*64 + j];
    out[token*64 + j] = Mf + (z - Mf)*ssen[g][j >> 2];
}

// ---------------- launch ----------------
extern "C" void kernel_launch(void* const* d_in, const int* in_sizes, int n_in,
                              void* d_out, int out_size){
    const float* M          = (const float*)d_in[0];
    const int*   token_ids  = (const int*)  d_in[1];
    const float* blk_w_qkv  = (const float*)d_in[2];
    const float* blk_b_qkv  = (const float*)d_in[3];
    const float* blk_w_out  = (const float*)d_in[4];
    const float* blk_b_out  = (const float*)d_in[5];
    const float* cross_w_qkv= (const float*)d_in[6];
    const float* cross_b_qkv= (const float*)d_in[7];
    const float* cross_w_out= (const float*)d_in[8];
    const float* cross_b_out= (const float*)d_in[9];
    const float* ln1g = (const float*)d_in[10];
    const float* ln1b = (const float*)d_in[11];
    const float* fw1  = (const float*)d_in[12];
    const float* fb1  = (const float*)d_in[13];
    const float* fw2  = (const float*)d_in[14];
    const float* fb2  = (const float*)d_in[15];
    const float* ln2g = (const float*)d_in[16];
    const float* ln2b = (const float*)d_in[17];
    const float* sbase= (const float*)d_in[18];
    const float* taff = (const float*)d_in[19];
    const float* sw1  = (const float*)d_in[20];
    const float* sb1  = (const float*)d_in[21];
    const float* sw2  = (const float*)d_in[22];
    const float* sb2  = (const float*)d_in[23];
    float* out = (float*)d_out;

    k2_blk_attn<<<512, 256>>>(M, blk_w_qkv, blk_b_qkv);
    k3_proj_cqkv<<<BT/4, 256>>>(blk_w_out, blk_b_out, cross_w_qkv, cross_b_qkv);
    k4_cross_attn<<<128, 256>>>();
    dim3 g5(BB, 4, 4);
    k5_entropy<<<g5, 128>>>();
    k6_final<<<BT/4, 256>>>(M, token_ids, cross_w_out, cross_b_out,
                            ln1g, ln1b, fw1, fb1, fw2, fb2, ln2g, ln2b,
                            sbase, taff, sw1, sb1, sw2, sb2, out);
}

// round 5
// speedup vs baseline: 1.0471x; 1.0471x over previous
#include <cuda_runtime.h>
#include <math.h>

#define BB 16
#define TT 512
#define BT (BB*TT)
#define LOG2E 1.4426950408889634f

// ---------------- scratch (device globals; no allocation) ----------------
__device__ __align__(16) float g_o [BT*64];          // block-attn out [token][n*4+h*2+d]
__device__ __align__(16) float g_ab[BT*64];          // all_blocks
__device__ __align__(16) float g_cq[BT*64];          // cross q/k/v, [token][h*8+d]
__device__ __align__(16) float g_ck[BT*64];
__device__ __align__(16) float g_cv[BT*64];
__device__ __align__(16) float g_co[BT*64];          // cross attn out
__device__ float g_m [BB*8*TT];                      // log2-domain softmax bound [b*8+h][t]
__device__ float g_l [BB*8*TT];                      // softmax denom (exp2 sums)
__device__ float g_entp[BT*8];                       // entropy partials per s-chunk

__device__ __forceinline__ float ex2(float x){
    float r; asm("ex2.approx.ftz.f32 %0, %1;" : "=f"(r) : "f"(x)); return r;
}
__device__ __forceinline__ float gelu_exact(float x){
    return 0.5f*x*(1.0f + erff(x*0.70710678118654752f));
}

// ---------------- K2: fused block QKV + block attention (d=2) ----------------
// One CTA per (b, n, h, qchunk): 1024 CTAs, 256 thr, 1 query/thread.
// Single-pass softmax with Cauchy-Schwarz bound (log2 domain).
__global__ void k2_blk_attn(const float* __restrict__ M,
                            const float* __restrict__ w,    // [16,12,4]
                            const float* __restrict__ bq){  // [16,12]
    __shared__ __align__(16) float4 skv[TT];  // {k0,k1,v0,v1} per s
    __shared__ float red[8];
    int bid = blockIdx.x;                     // ((b*16+n)*2+h)*2+qc
    int qc = bid & 1;
    int h  = (bid >> 1) & 1;
    int n  = (bid >> 2) & 15;
    int b  = bid >> 6;
    int tid = threadIdx.x;
    int br = n >> 2, bc = n & 3;
    float wq[2][4], wk[2][4], wv[2][4], bqv[2], bkv[2], bvv[2];
    #pragma unroll
    for (int e = 0; e < 2; e++){
        int rq = h*2 + e, rk = 4 + h*2 + e, rv = 8 + h*2 + e;
        #pragma unroll
        for (int c = 0; c < 4; c++){
            wq[e][c] = w[n*48 + rq*4 + c];
            wk[e][c] = w[n*48 + rk*4 + c];
            wv[e][c] = w[n*48 + rv*4 + c];
        }
        bqv[e] = bq[n*12 + rq]; bkv[e] = bq[n*12 + rk]; bvv[e] = bq[n*12 + rv];
    }
    const float qscale = 0.70710678118654752f * LOG2E;   // (1/sqrt(2))*log2(e)
    float q0 = 0.f, q1 = 0.f;
    float knmax = 0.f;
    #pragma unroll
    for (int qi = 0; qi < 2; qi++){
        int t = tid + qi*256;
        const float* Mtok = M + ((size_t)(b*TT + t))*64;
        float x0 = Mtok[(2*br+0)*8 + 2*bc+0];
        float x1 = Mtok[(2*br+0)*8 + 2*bc+1];
        float x2 = Mtok[(2*br+1)*8 + 2*bc+0];
        float x3 = Mtok[(2*br+1)*8 + 2*bc+1];
        float4 kv;
        kv.x = bkv[0] + wk[0][0]*x0 + wk[0][1]*x1 + wk[0][2]*x2 + wk[0][3]*x3;
        kv.y = bkv[1] + wk[1][0]*x0 + wk[1][1]*x1 + wk[1][2]*x2 + wk[1][3]*x3;
        kv.z = bvv[0] + wv[0][0]*x0 + wv[0][1]*x1 + wv[0][2]*x2 + wv[0][3]*x3;
        kv.w = bvv[1] + wv[1][0]*x0 + wv[1][1]*x1 + wv[1][2]*x2 + wv[1][3]*x3;
        skv[t] = kv;
        knmax = fmaxf(knmax, kv.x*kv.x + kv.y*kv.y);
        if (qi == qc){
            q0 = (bqv[0] + wq[0][0]*x0 + wq[0][1]*x1 + wq[0][2]*x2 + wq[0][3]*x3)*qscale;
            q1 = (bqv[1] + wq[1][0]*x0 + wq[1][1]*x1 + wq[1][2]*x2 + wq[1][3]*x3)*qscale;
        }
    }
    #pragma unroll
    for (int o = 16; o > 0; o >>= 1)
        knmax = fmaxf(knmax, __shfl_xor_sync(0xffffffffu, knmax, o));
    if ((tid & 31) == 0) red[tid >> 5] = knmax;
    __syncthreads();
    float kn = red[0];
    #pragma unroll
    for (int i = 1; i < 8; i++) kn = fmaxf(kn, red[i]);
    float m0 = sqrtf(q0*q0 + q1*q1) * sqrtf(kn);   // log2-domain upper bound
    float l0 = 0.f, a00 = 0.f, a01 = 0.f;
    #pragma unroll 4
    for (int s = 0; s < TT; s++){
        float4 kv = skv[s];
        float p0 = ex2(fmaf(q0, kv.x, fmaf(q1, kv.y, -m0)));
        l0 += p0; a00 += p0*kv.z; a01 += p0*kv.w;
    }
    float inv0 = 1.f/l0;
    int t0 = qc*256 + tid;
    int o0 = (b*TT + t0)*64 + n*4 + h*2;
    g_o[o0] = a00*inv0; g_o[o0+1] = a01*inv0;
}

// ---------------- K3: block-out proj + cross QKV (4 tokens per CTA) ----------------
__global__ void k3_proj_cqkv(const float* __restrict__ wout, // [16,4,4]
                             const float* __restrict__ bout, // [16,4]
                             const float* __restrict__ cw,   // [192,64]
                             const float* __restrict__ cb){  // [192]
    __shared__ __align__(16) float so [4][64];
    __shared__ __align__(16) float sab[4][64];
    int tid = threadIdx.x;
    int g = tid >> 6, j = tid & 63;
    int token = blockIdx.x*4 + g;
    so[g][j] = g_o[token*64 + j];
    __syncthreads();
    int n = j >> 2, e = j & 3;
    const float* wr = &wout[n*16 + e*4];
    float acc = bout[j] + wr[0]*so[g][n*4] + wr[1]*so[g][n*4+1]
              + wr[2]*so[g][n*4+2] + wr[3]*so[g][n*4+3];
    sab[g][j] = acc;
    g_ab[token*64 + j] = acc;
    __syncthreads();
    const float4* x4 = (const float4*)sab[g];
    #pragma unroll
    for (int rr = 0; rr < 3; rr++){
        int r = rr*64 + j;
        const float4* w4 = (const float4*)&cw[r*64];
        float acc2 = cb[r];
        #pragma unroll
        for (int k = 0; k < 16; k++){
            float4 w = w4[k], x = x4[k];
            acc2 += w.x*x.x + w.y*x.y + w.z*x.z + w.w*x.w;
        }
        float* dst = (rr==0) ? g_cq : (rr==1) ? g_ck : g_cv;
        dst[token*64 + j] = acc2;
    }
}

// ---------------- K4: cross attention (d=8) ----------------
// One CTA per (b, h, qchunk): 256 CTAs, 256 thr, 1 query/thread.
__global__ void k4_cross_attn(){
    __shared__ __align__(16) float sk[TT*8];
    __shared__ __align__(16) float sv[TT*8];
    __shared__ float red[8];
    int bid = blockIdx.x;                    // (b*8+h)*2+qc
    int qc = bid & 1;
    int h  = (bid >> 1) & 7;
    int b  = bid >> 4;
    int tid = threadIdx.x;
    float knmax = 0.f;
    for (int i = tid; i < TT; i += 256){
        int src = (b*TT + i)*64 + h*8;
        float4 ka = *(const float4*)&g_ck[src];
        float4 kb = *(const float4*)&g_ck[src+4];
        ((float4*)sk)[i*2  ] = ka;
        ((float4*)sk)[i*2+1] = kb;
        knmax = fmaxf(knmax, ka.x*ka.x + ka.y*ka.y + ka.z*ka.z + ka.w*ka.w
                           + kb.x*kb.x + kb.y*kb.y + kb.z*kb.z + kb.w*kb.w);
        ((float4*)sv)[i*2  ] = *(const float4*)&g_cv[src];
        ((float4*)sv)[i*2+1] = *(const float4*)&g_cv[src+4];
    }
    #pragma unroll
    for (int o = 16; o > 0; o >>= 1)
        knmax = fmaxf(knmax, __shfl_xor_sync(0xffffffffu, knmax, o));
    if ((tid & 31) == 0) red[tid >> 5] = knmax;
    __syncthreads();
    float kn = red[0];
    #pragma unroll
    for (int i = 1; i < 8; i++) kn = fmaxf(kn, red[i]);
    float mk = sqrtf(kn);
    const float qscale = 0.35355339059327376f * LOG2E;   // (1/sqrt(8))*log2(e)
    int t = qc*256 + tid;
    float q[8];
    {
        float4 qa = *(const float4*)&g_cq[(b*TT+t)*64 + h*8];
        float4 qb = *(const float4*)&g_cq[(b*TT+t)*64 + h*8 + 4];
        q[0]=qa.x*qscale; q[1]=qa.y*qscale; q[2]=qa.z*qscale; q[3]=qa.w*qscale;
        q[4]=qb.x*qscale; q[5]=qb.y*qscale; q[6]=qb.z*qscale; q[7]=qb.w*qscale;
    }
    float qn = 0.f;
    #pragma unroll
    for (int d = 0; d < 8; d++) qn += q[d]*q[d];
    float m = sqrtf(qn) * mk;
    float l = 0.f;
    float a[8];
    #pragma unroll
    for (int d = 0; d < 8; d++) a[d] = 0.f;
    #pragma unroll 2
    for (int s = 0; s < TT; s++){
        const float4* kr = (const float4*)&sk[s*8];
        float4 k0 = kr[0], k1 = kr[1];
        float x = -m;
        x = fmaf(q[0],k0.x, fmaf(q[1],k0.y, fmaf(q[2],k0.z, fmaf(q[3],k0.w,
            fmaf(q[4],k1.x, fmaf(q[5],k1.y, fmaf(q[6],k1.z, fmaf(q[7],k1.w, x))))))));
        float p = ex2(x);
        const float4* vr = (const float4*)&sv[s*8];
        float4 v0 = vr[0], v1 = vr[1];
        l += p;
        a[0]+=p*v0.x; a[1]+=p*v0.y; a[2]+=p*v0.z; a[3]+=p*v0.w;
        a[4]+=p*v1.x; a[5]+=p*v1.y; a[6]+=p*v1.z; a[7]+=p*v1.w;
    }
    float inv = 1.f/l;
    int ob = (b*TT+t)*64 + h*8;
    #pragma unroll
    for (int d = 0; d < 8; d++) g_co[ob+d] = a[d]*inv;
    g_m[(b*8+h)*TT + t] = m;
    g_l[(b*8+h)*TT + t] = l;
}

// ---------------- K5: entropy of head-averaged attention (score recompute) ----------------
// grid (16, 8 s-chunks of 64, 4 q-chunks of 128), 128 threads.
// p contribution folded into the exp2 arg: p += exp2(dot'' - c_h), c_h = m'' + 3 + log2(l).
__global__ void k5_entropy(){
    __shared__ __align__(16) float sks[64*64];
    int b  = blockIdx.x;
    int s0 = blockIdx.y * 64;
    int q0 = blockIdx.z * 128;
    int tid = threadIdx.x;                   // 128
    for (int i = tid; i < 64*16; i += 128){  // float4s
        int row = i >> 4, part = i & 15;
        ((float4*)sks)[i] = *(const float4*)&g_ck[(b*TT + s0 + row)*64 + part*4];
    }
    __syncthreads();
    int t = q0 + tid;
    const float qscale = 0.35355339059327376f * LOG2E;
    float4 qv[16];
    const float4* qg = (const float4*)&g_cq[(b*TT+t)*64];
    #pragma unroll
    for (int i = 0; i < 16; i++){
        float4 q = qg[i];
        q.x *= qscale; q.y *= qscale; q.z *= qscale; q.w *= qscale;
        qv[i] = q;
    }
    float ch[8];
    #pragma unroll
    for (int h = 0; h < 8; h++){
        ch[h] = g_m[(b*8+h)*TT + t] + 3.0f + __log2f(g_l[(b*8+h)*TT + t]);
    }
    float ent = 0.f;
    for (int s = 0; s < 64; s++){
        const float4* kr = (const float4*)&sks[s*64];
        float p = 0.f;
        #pragma unroll
        for (int h = 0; h < 8; h++){
            float4 k0 = kr[2*h], k1 = kr[2*h+1];
            float4 a0 = qv[2*h], a1 = qv[2*h+1];
            float d = -ch[h];
            d = fmaf(a0.x,k0.x, fmaf(a0.y,k0.y, fmaf(a0.z,k0.z, fmaf(a0.w,k0.w,
                fmaf(a1.x,k1.x, fmaf(a1.y,k1.y, fmaf(a1.z,k1.z, fmaf(a1.w,k1.w, d))))))));
            p += ex2(d);
        }
        ent += p * __logf(p + 1e-9f);
    }
    g_entp[(b*TT+t)*8 + blockIdx.y] = -ent;
}

// ---------------- K6: cross-out proj + LN1 + FFN + LN2 + sens MLP + gate ----------------
__global__ void k6_final(const float* __restrict__ M, const int* __restrict__ tok_ids,
                         const float* __restrict__ cwout, const float* __restrict__ cbout,
                         const float* __restrict__ ln1g, const float* __restrict__ ln1b,
                         const float* __restrict__ fw1,  const float* __restrict__ fb1,
                         const float* __restrict__ fw2,  const float* __restrict__ fb2,
                         const float* __restrict__ ln2g, const float* __restrict__ ln2b,
                         const float* __restrict__ sbase,const float* __restrict__ taff,
                         const float* __restrict__ sw1,  const float* __restrict__ sb1,
                         const float* __restrict__ sw2,  const float* __restrict__ sb2,
                         float* __restrict__ out){
    __shared__ __align__(16) float sx [4][64];
    __shared__ __align__(16) float sy [4][64];
    __shared__ __align__(16) float sh1[4][256];
    __shared__ float sfeat[4][17];
    __shared__ float shh[4][32];
    __shared__ float ssen[4][16];
    int tid = threadIdx.x;
    int g = tid >> 6, j = tid & 63;
    int token = blockIdx.x*4 + g;
    sx[g][j] = g_co[token*64 + j];
    __syncthreads();
    float acc = cbout[j];
    {
        const float4* w4 = (const float4*)&cwout[j*64];
        const float4* x4 = (const float4*)sx[g];
        #pragma unroll
        for (int k = 0; k < 16; k++){
            float4 w = w4[k], x = x4[k];
            acc += w.x*x.x + w.y*x.y + w.z*x.z + w.w*x.w;
        }
    }
    float xj = g_ab[token*64 + j] + acc;
    __syncthreads();
    sx[g][j] = xj;
    __syncthreads();
    float sum = 0.f, ss = 0.f;
    #pragma unroll
    for (int k = 0; k < 64; k++){ float v = sx[g][k]; sum += v; ss += v*v; }
    float mu  = sum*(1.f/64.f);
    float var = ss*(1.f/64.f) - mu*mu;
    float rs  = rsqrtf(var + 1e-5f);
    float y = (xj - mu)*rs*ln1g[j] + ln1b[j];
    sy[g][j] = y;
    __syncthreads();
    #pragma unroll
    for (int rr = 0; rr < 4; rr++){
        int r = rr*64 + j;
        float a = fb1[r];
        const float4* w4 = (const float4*)&fw1[r*64];
        const float4* x4 = (const float4*)sy[g];
        #pragma unroll
        for (int k = 0; k < 16; k++){ float4 w=w4[k], x=x4[k]; a += w.x*x.x + w.y*x.y + w.z*x.z + w.w*x.w; }
        sh1[g][r] = gelu_exact(a);
    }
    __syncthreads();
    float a2 = fb2[j];
    {
        const float4* w4 = (const float4*)&fw2[j*256];
        const float4* x4 = (const float4*)sh1[g];
        #pragma unroll
        for (int k = 0; k < 64; k++){ float4 w=w4[k], x=x4[k]; a2 += w.x*x.x + w.y*x.y + w.z*x.z + w.w*x.w; }
    }
    float x2 = y + a2;
    __syncthreads();
    sx[g][j] = x2;
    __syncthreads();
    sum = 0.f; ss = 0.f;
    #pragma unroll
    for (int k = 0; k < 64; k++){ float v = sx[g][k]; sum += v; ss += v*v; }
    mu  = sum*(1.f/64.f);
    var = ss*(1.f/64.f) - mu*mu;
    rs  = rsqrtf(var + 1e-5f);
    float z = (x2 - mu)*rs*ln2g[j] + ln2b[j];
    if (j < 16) sfeat[g][j] = taff[(long long)tok_ids[token]*16 + j];
    if (j == 16){
        float e = 0.f;
        #pragma unroll
        for (int c = 0; c < 8; c++) e += g_entp[token*8 + c];
        sfeat[g][16] = e;
    }
    __syncthreads();
    if (j < 32){
        float a = sb1[j];
        #pragma unroll
        for (int k = 0; k < 17; k++) a += sw1[j*17+k]*sfeat[g][k];
        shh[g][j] = gelu_exact(a);
    }
    __syncthreads();
    if (j < 16){
        float a = sb2[j];
        #pragma unroll
        for (int k = 0; k < 32; k++) a += sw2[j*32+k]*shh[g][k];
        ssen[g][j] = sbase[j] / (1.f + __expf(-a));
    }
    __syncthreads();
    float Mf = M[token*64 + j];
    out[token*64 + j] = Mf + (z - Mf)*ssen[g][j >> 2];
}

// ---------------- launch ----------------
extern "C" void kernel_launch(void* const* d_in, const int* in_sizes, int n_in,
                              void* d_out, int out_size){
    const float* M          = (const float*)d_in[0];
    const int*   token_ids  = (const int*)  d_in[1];
    const float* blk_w_qkv  = (const float*)d_in[2];
    const float* blk_b_qkv  = (const float*)d_in[3];
    const float* blk_w_out  = (const float*)d_in[4];
    const float* blk_b_out  = (const float*)d_in[5];
    const float* cross_w_qkv= (const float*)d_in[6];
    const float* cross_b_qkv= (const float*)d_in[7];
    const float* cross_w_out= (const float*)d_in[8];
    const float* cross_b_out= (const float*)d_in[9];
    const float* ln1g = (const float*)d_in[10];
    const float* ln1b = (const float*)d_in[11];
    const float* fw1  = (const float*)d_in[12];
    const float* fb1  = (const float*)d_in[13];
    const float* fw2  = (const float*)d_in[14];
    const float* fb2  = (const float*)d_in[15];
    const float* ln2g = (const float*)d_in[16];
    const float* ln2b = (const float*)d_in[17];
    const float* sbase= (const float*)d_in[18];
    const float* taff = (const float*)d_in[19];
    const float* sw1  = (const float*)d_in[20];
    const float* sb1  = (const float*)d_in[21];
    const float* sw2  = (const float*)d_in[22];
    const float* sb2  = (const float*)d_in[23];
    float* out = (float*)d_out;

    k2_blk_attn<<<1024, 256>>>(M, blk_w_qkv, blk_b_qkv);
    k3_proj_cqkv<<<BT/4, 256>>>(blk_w_out, blk_b_out, cross_w_qkv, cross_b_qkv);
    k4_cross_attn<<<256, 256>>>();
    dim3 g5(BB, 8, 4);
    k5_entropy<<<g5, 128>>>();
    k6_final<<<BT/4, 256>>>(M, token_ids, cross_w_out, cross_b_out,
                            ln1g, ln1b, fw1, fb1, fw2, fb2, ln2g, ln2b,
                            sbase, taff, sw1, sb1, sw2, sb2, out);
}